// round 11
// baseline (speedup 1.0000x reference)
#include <cuda_runtime.h>

// ---------------------------------------------------------------------------
// ComplexSwinAttention, fused. OUTPUT = REAL PART ONLY (out_size = B*16384
// float32; established via the 0.7071 rel_err signature in round 10 and the
// 2x-overrun crashes of rounds 1-5).
// Kernel A: per-window qkv + complex attention -> complex planar staging in
//           __device__ static scratch (statics exonerated in round 4).
// Kernel B: per-window Wproj; writes ONLY Re(y) to d_out.
// Binding: size-rank; within each pair lower original index = REAL.
// ---------------------------------------------------------------------------

__device__ float g_att_r[16777216];   // [b][ch][pos] real
__device__ float g_att_i[16777216];   // [b][ch][pos] imag

__device__ __forceinline__ float gldf(const float* p, long off, long lim)
{
    return (off >= 0 && off < lim) ? __ldg(p + off) : 0.f;
}
__device__ __forceinline__ int gldi(const int* p, long off, long lim)
{
    return (off >= 0 && off < lim) ? __ldg(p + off) : 0;
}

// ---------------------------------------------------------------------------
// Kernel A. 512 threads/CTA, one CTA per window. Dyn smem (floats):
//  xr[16384] xi[16384] qr..vi[6*2048] sr/si[2*4160] = 53376 floats = 213504 B
// ---------------------------------------------------------------------------
__global__ __launch_bounds__(512) void fused_attn(
    const float* __restrict__ xr_g, const float* __restrict__ xi_g,
    const float* __restrict__ wq_r, const float* __restrict__ wq_i,
    const float* __restrict__ bt,   const int* __restrict__ ri,
    long xlim, long wqlim, long btlim, long rilim)
{
    extern __shared__ __align__(16) float smA[];
    float* xr = smA;
    float* xi = xr + 16384;
    float* qr = xi + 16384;
    float* qi = qr + 2048;
    float* kr = qi + 2048;
    float* ki = kr + 2048;
    float* vr = ki + 2048;
    float* vi = vr + 2048;
    float* sr = vi + 2048;   // [64][65]
    float* si = sr + 4160;

    const int b = blockIdx.x, t = threadIdx.x;
    const long xbase = (long)b * 16384;
    const float scale = 0.17677669529663687f;   // 32^-0.5

    for (int idx = t; idx < 16384; idx += 512) {
        xr[idx] = gldf(xr_g, xbase + idx, xlim);
        xi[idx] = gldf(xi_g, xbase + idx, xlim);
    }
    __syncthreads();

    for (int h = 0; h < 8; ++h) {
        // ---- q/k/v rows for this head: thread = (row r, 4 positions) ----
        {
            const int r = t >> 4, p0 = (t & 15) << 2;
            #pragma unroll
            for (int blkq = 0; blkq < 3; ++blkq) {
                const long wb = (long)(blkq * 256 + h * 32 + r) * 256;
                float ar[4] = {}, ai[4] = {};
                #pragma unroll 4
                for (int c = 0; c < 256; ++c) {
                    float wRc = gldf(wq_r, wb + c, wqlim);
                    float wIc = gldf(wq_i, wb + c, wqlim);
                    float4 x4r = *(const float4*)&xr[c * 64 + p0];   // smem
                    float4 x4i = *(const float4*)&xi[c * 64 + p0];
                    float xR[4] = {x4r.x, x4r.y, x4r.z, x4r.w};
                    float xI[4] = {x4i.x, x4i.y, x4i.z, x4i.w};
                    #pragma unroll
                    for (int j = 0; j < 4; ++j) {
                        ar[j] = fmaf(wRc,  xR[j], ar[j]);
                        ar[j] = fmaf(-wIc, xI[j], ar[j]);
                        ai[j] = fmaf(wRc,  xI[j], ai[j]);
                        ai[j] = fmaf(wIc,  xR[j], ai[j]);
                    }
                }
                float* dR = (blkq == 0) ? qr : ((blkq == 1) ? kr : vr);
                float* dI = (blkq == 0) ? qi : ((blkq == 1) ? ki : vi);
                *(float4*)&dR[r * 64 + p0] = make_float4(ar[0], ar[1], ar[2], ar[3]);
                *(float4*)&dI[r * 64 + p0] = make_float4(ai[0], ai[1], ai[2], ai[3]);
            }
        }
        __syncthreads();

        // ---- S = scale * q conj(k)^T + bias ; micro 2n x 4m ----
        {
            const int n0 = (t >> 4) << 1, m0 = (t & 15) << 2;
            float accr[2][4] = {}, acci[2][4] = {};
            #pragma unroll 8
            for (int d = 0; d < 32; ++d) {
                float q0r = qr[d * 64 + n0],     q0i = qi[d * 64 + n0];
                float q1r = qr[d * 64 + n0 + 1], q1i = qi[d * 64 + n0 + 1];
                float4 k4r = *(const float4*)&kr[d * 64 + m0];
                float4 k4i = *(const float4*)&ki[d * 64 + m0];
                float kR[4] = {k4r.x, k4r.y, k4r.z, k4r.w};
                float kI[4] = {k4i.x, k4i.y, k4i.z, k4i.w};
                #pragma unroll
                for (int j = 0; j < 4; ++j) {
                    accr[0][j] = fmaf(q0r, kR[j], accr[0][j]);
                    accr[0][j] = fmaf(q0i, kI[j], accr[0][j]);
                    acci[0][j] = fmaf(q0i, kR[j], acci[0][j]);
                    acci[0][j] = fmaf(-q0r, kI[j], acci[0][j]);
                    accr[1][j] = fmaf(q1r, kR[j], accr[1][j]);
                    accr[1][j] = fmaf(q1i, kI[j], accr[1][j]);
                    acci[1][j] = fmaf(q1i, kR[j], acci[1][j]);
                    acci[1][j] = fmaf(-q1r, kI[j], acci[1][j]);
                }
            }
            #pragma unroll
            for (int i = 0; i < 2; ++i) {
                int n = n0 + i;
                #pragma unroll
                for (int j = 0; j < 4; ++j) {
                    int m = m0 + j;
                    int riv = gldi(ri, (long)(n << 6) + m, rilim);
                    riv = riv < 0 ? 0 : (riv > 224 ? 224 : riv);
                    float bv = gldf(bt, (long)riv * 8 + h, btlim);
                    sr[n * 65 + m] = fmaf(accr[i][j], scale, bv);
                    si[n * 65 + m] = acci[i][j] * scale;
                }
            }
        }
        __syncthreads();

        // ---- magnitude softmax + rescale (8 threads/row, 8 cols each) ----
        {
            const int row = t >> 3, c0 = (t & 7) << 3;
            float mags[8], mx = -1e30f;
            #pragma unroll
            for (int c = 0; c < 8; ++c) {
                float arr = sr[row * 65 + c0 + c], aii = si[row * 65 + c0 + c];
                float mg = sqrtf(fmaf(arr, arr, aii * aii));
                mags[c] = mg;
                mx = fmaxf(mx, mg);
            }
            mx = fmaxf(mx, __shfl_xor_sync(0xffffffffu, mx, 1));
            mx = fmaxf(mx, __shfl_xor_sync(0xffffffffu, mx, 2));
            mx = fmaxf(mx, __shfl_xor_sync(0xffffffffu, mx, 4));
            float e[8], ssum = 0.f;
            #pragma unroll
            for (int c = 0; c < 8; ++c) { e[c] = __expf(mags[c] - mx); ssum += e[c]; }
            ssum += __shfl_xor_sync(0xffffffffu, ssum, 1);
            ssum += __shfl_xor_sync(0xffffffffu, ssum, 2);
            ssum += __shfl_xor_sync(0xffffffffu, ssum, 4);
            float inv = 1.0f / ssum;
            #pragma unroll
            for (int c = 0; c < 8; ++c) {
                float w = (e[c] * inv) / (mags[c] + 1e-8f);
                sr[row * 65 + c0 + c] *= w;
                si[row * 65 + c0 + c] *= w;
            }
        }
        __syncthreads();

        // ---- out = S @ V (64 n x 32 d) -> complex staging in statics ----
        {
            const int n = t & 63, d0 = (t >> 6) << 2;
            float o_r[4] = {}, o_i[4] = {};
            #pragma unroll 8
            for (int m = 0; m < 64; ++m) {
                float srv = sr[n * 65 + m], siv = si[n * 65 + m];
                #pragma unroll
                for (int j = 0; j < 4; ++j) {
                    float vrj = vr[(d0 + j) * 64 + m];
                    float vij = vi[(d0 + j) * 64 + m];
                    o_r[j] = fmaf(srv,  vrj, o_r[j]);
                    o_r[j] = fmaf(-siv, vij, o_r[j]);
                    o_i[j] = fmaf(srv,  vij, o_i[j]);
                    o_i[j] = fmaf(siv,  vrj, o_i[j]);
                }
            }
            #pragma unroll
            for (int j = 0; j < 4; ++j) {
                int ch = (h << 5) + d0 + j;
                long o = (long)b * 16384 + (long)ch * 64 + n;  // < 16777216
                g_att_r[o] = o_r[j];
                g_att_i[o] = o_i[j];
            }
        }
        __syncthreads();
    }
}

// ---------------------------------------------------------------------------
// Kernel B. 512 threads. Dyn smem 131072 B. Reads complex staging from
// statics; writes ONLY Re(y) to d_out.
// ---------------------------------------------------------------------------
__global__ __launch_bounds__(512) void proj_kernel(
    const float* __restrict__ wp_r, const float* __restrict__ wp_i,
    float* __restrict__ io, long wplim, long olim)
{
    extern __shared__ __align__(16) float smB[];
    float* ar = smB;
    float* ai = ar + 16384;

    const int b = blockIdx.x, t = threadIdx.x;
    const long base = (long)b * 16384;

    for (int idx = t; idx < 16384; idx += 512) {
        ar[idx] = g_att_r[base + idx];
        ai[idx] = g_att_i[base + idx];
    }
    __syncthreads();

    const int o = t & 255, ph = t >> 8;        // ph in {0,1}
    const long wb = (long)o * 256;

    #pragma unroll 1
    for (int pass = 0; pass < 2; ++pass) {
        const int p0 = ph * 32 + pass * 16;
        float yrv[16] = {};
        #pragma unroll 4
        for (int c = 0; c < 256; ++c) {
            float wRc = gldf(wp_r, wb + c, wplim);
            float wIc = gldf(wp_i, wb + c, wplim);
            const float* arow = &ar[c * 64 + p0];
            const float* airo = &ai[c * 64 + p0];
            #pragma unroll
            for (int q4 = 0; q4 < 4; ++q4) {
                float4 a4r = *(const float4*)&arow[q4 * 4];
                float4 a4i = *(const float4*)&airo[q4 * 4];
                float aR[4] = {a4r.x, a4r.y, a4r.z, a4r.w};
                float aI[4] = {a4i.x, a4i.y, a4i.z, a4i.w};
                #pragma unroll
                for (int l = 0; l < 4; ++l) {
                    int idx = q4 * 4 + l;
                    // Re(y) = wR*aR - wI*aI
                    yrv[idx] = fmaf(wRc,  aR[l], yrv[idx]);
                    yrv[idx] = fmaf(-wIc, aI[l], yrv[idx]);
                }
            }
        }
        #pragma unroll
        for (int pq = 0; pq < 16; ++pq) {
            long f = base + (long)o * 64 + p0 + pq;
            if (f < olim) io[f] = yrv[pq];
        }
    }
}

// ---------------------------------------------------------------------------
extern "C" void kernel_launch(void* const* d_in, const int* in_sizes, int n_in,
                              void* d_out, int out_size)
{
    // Rank-based binding (stable sort by size desc):
    // ranks 0,1 = x pair; 2,3 = w_qkv pair; 4,5 = w_proj pair;
    // 6 = rel_index; 7 = bias_table. Within pair: lower index = REAL.
    int ord[16];
    int m = n_in < 16 ? n_in : 16;
    for (int i = 0; i < m; ++i) ord[i] = i;
    for (int i = 1; i < m; ++i) {
        int key = ord[i];
        long ks = in_sizes[key];
        int j = i - 1;
        while (j >= 0 && (long)in_sizes[ord[j]] < ks) { ord[j + 1] = ord[j]; --j; }
        ord[j + 1] = key;
    }

    const float *x_r, *x_i, *wq_r, *wq_i, *wp_r, *wp_i, *bt;
    const int* ri;
    long sx;
    long wqlim, wplim, btlim, rilim;

    if (m >= 8) {
        int a0 = ord[0], a1 = ord[1];
        int b0 = ord[2], b1 = ord[3];
        int c0 = ord[4], c1 = ord[5];
        int r0 = ord[6], s0 = ord[7];
        if (a0 > a1) { int tt = a0; a0 = a1; a1 = tt; }
        if (b0 > b1) { int tt = b0; b0 = b1; b1 = tt; }
        if (c0 > c1) { int tt = c0; c0 = c1; c1 = tt; }
        x_r  = (const float*)d_in[a0]; x_i  = (const float*)d_in[a1];
        wq_r = (const float*)d_in[b0]; wq_i = (const float*)d_in[b1];
        wp_r = (const float*)d_in[c0]; wp_i = (const float*)d_in[c1];
        ri   = (const int*)d_in[r0];   bt   = (const float*)d_in[s0];
        sx    = in_sizes[a0];
        wqlim = in_sizes[b0] < 196608 ? in_sizes[b0] : 196608;
        wplim = in_sizes[c0] < 65536  ? in_sizes[c0] : 65536;
        rilim = in_sizes[r0] < 4096   ? in_sizes[r0] : 4096;
        btlim = in_sizes[s0] < 1800   ? in_sizes[s0] : 1800;
    } else {
        x_r  = (const float*)d_in[0]; x_i  = (const float*)d_in[1];
        wq_r = (const float*)d_in[2]; wq_i = (const float*)d_in[3];
        wp_r = (const float*)d_in[4]; wp_i = (const float*)d_in[5];
        bt   = (const float*)d_in[6]; ri   = (const int*)d_in[7];
        sx = 16777216; wqlim = 196608; wplim = 65536; rilim = 4096; btlim = 1800;
    }
    float* out = (float*)d_out;

    // Geometry: one window = 256 ch x 64 pos = 16384 floats per plane.
    long B = sx / 16384;
    if (B < 1) B = 1;
    if (B > 1024) B = 1024;           // static scratch sized for 1024 windows
    long xlim = B * 16384;
    if (xlim > sx) xlim = sx;

    // Output = REAL PART ONLY: B*16384 float32 elements.
    long olim = (long)out_size;
    long need = B * 16384;
    if (olim > need) olim = need;
    if (olim < 0) olim = 0;

    const int smA_bytes = 213504;          // 53376 floats
    const int smB_bytes = 131072;          // 32768 floats
    cudaFuncSetAttribute(fused_attn,
                         cudaFuncAttributeMaxDynamicSharedMemorySize, smA_bytes);
    cudaFuncSetAttribute(proj_kernel,
                         cudaFuncAttributeMaxDynamicSharedMemorySize, smB_bytes);

    fused_attn<<<(unsigned)B, 512, smA_bytes>>>(x_r, x_i, wq_r, wq_i, bt, ri,
                                                xlim, wqlim, btlim, rilim);
    proj_kernel<<<(unsigned)B, 512, smB_bytes>>>(wp_r, wp_i, out, olim ? wplim : 0, olim);
}

// round 12
// speedup vs baseline: 1.8769x; 1.8769x over previous
#include <cuda_runtime.h>

// ---------------------------------------------------------------------------
// ComplexSwinAttention — 3-kernel pipeline with packed f32x2 FMA (FFMA2).
//  K1 qkv_gemm : Wqkv(768x256 cplx) @ X(256x65536 cplx) -> g_qkv planar
//  K2 attn     : per (window, head) complex attention     -> g_att planar
//  K3 proj_gemm: Wproj(256x256 cplx) @ g_att, REAL part  -> d_out
// Output = real part only, [b][c][h][w] (established round 11).
// Binding: size-rank, lower index in pair = real (established round 11).
// ---------------------------------------------------------------------------

typedef unsigned long long ull;

__device__ float g_qkv_r[50331648];   // [768][65536]
__device__ float g_qkv_i[50331648];
__device__ float g_att_r[16777216];   // [256][65536]
__device__ float g_att_i[16777216];

__device__ __forceinline__ float gldf(const float* p, long off, long lim)
{
    return (off >= 0 && off < lim) ? __ldg(p + off) : 0.f;
}
__device__ __forceinline__ int gldi(const int* p, long off, long lim)
{
    return (off >= 0 && off < lim) ? __ldg(p + off) : 0;
}
__device__ __forceinline__ float4 guarded_ld4(const float* p, long off, long lim)
{
    if (off >= 0 && off + 3 < lim) return *(const float4*)(p + off);
    return make_float4(0.f, 0.f, 0.f, 0.f);
}

__device__ __forceinline__ ull pk2(float lo, float hi)
{
    ull r; asm("mov.b64 %0,{%1,%2};" : "=l"(r) : "f"(lo), "f"(hi)); return r;
}
__device__ __forceinline__ ull ffma2(ull a, ull b, ull c)
{
    ull d; asm("fma.rn.f32x2 %0,%1,%2,%3;" : "=l"(d) : "l"(a), "l"(b), "l"(c));
    return d;
}

// ---------------------------------------------------------------------------
// K1: qkv complex GEMM. Tile 64 rows x 128 cols, K=256 in 16-steps.
// 256 threads; micro = 4 rows x 4 col-pairs (8 cols). Static smem 42.2 KB.
// X input layout: x[b][c][p] -> addr = (j>>6)*16384 + c*64 + (j&63), j=b*64+p.
// ---------------------------------------------------------------------------
__global__ __launch_bounds__(256) void qkv_gemm(
    const float* __restrict__ wr, const float* __restrict__ wi,
    const float* __restrict__ xr, const float* __restrict__ xi,
    long wlim, long xlim)
{
    __shared__ __align__(16) ull   w_rr[16][66], w_ii[16][66], w_ni[16][66];
    __shared__ __align__(16) float xs_r[16][132], xs_i[16][132];

    const int t = threadIdx.x;
    const long colBase = (long)blockIdx.x * 128;
    const int rowBase = blockIdx.y * 64;

    const int wrow = t >> 2, wk4 = (t & 3) << 2;
    const long wbase = (long)(rowBase + wrow) * 256 + wk4;

    const int k0a = t >> 5;            // 0..7 ; second slot k0a+8
    const int j0a = (t & 31) << 2;     // 0..124
    const long ja = colBase + j0a;
    const long jblk = (ja >> 6) * 16384 + (ja & 63);

    const int tx8 = (t & 15) << 3, ty4 = (t >> 4) << 2;

    ull c_re[4][4], c_im[4][4];
    #pragma unroll
    for (int i = 0; i < 4; ++i)
        #pragma unroll
        for (int j = 0; j < 4; ++j) { c_re[i][j] = 0ull; c_im[i][j] = 0ull; }

    for (int k0 = 0; k0 < 256; k0 += 16) {
        float4 wa = guarded_ld4(wr, wbase + k0, wlim);
        float4 wb = guarded_ld4(wi, wbase + k0, wlim);
        float4 xa0 = guarded_ld4(xr, jblk + (long)(k0 + k0a) * 64, xlim);
        float4 xb0 = guarded_ld4(xi, jblk + (long)(k0 + k0a) * 64, xlim);
        float4 xa1 = guarded_ld4(xr, jblk + (long)(k0 + k0a + 8) * 64, xlim);
        float4 xb1 = guarded_ld4(xi, jblk + (long)(k0 + k0a + 8) * 64, xlim);
        __syncthreads();
        {
            float wva[4] = {wa.x, wa.y, wa.z, wa.w};
            float wvb[4] = {wb.x, wb.y, wb.z, wb.w};
            #pragma unroll
            for (int q = 0; q < 4; ++q) {
                w_rr[wk4 + q][wrow] = pk2(wva[q], wva[q]);
                w_ii[wk4 + q][wrow] = pk2(wvb[q], wvb[q]);
                w_ni[wk4 + q][wrow] = pk2(-wvb[q], -wvb[q]);
            }
            *(float4*)&xs_r[k0a][j0a] = xa0;
            *(float4*)&xs_i[k0a][j0a] = xb0;
            *(float4*)&xs_r[k0a + 8][j0a] = xa1;
            *(float4*)&xs_i[k0a + 8][j0a] = xb1;
        }
        __syncthreads();
        #pragma unroll
        for (int kk = 0; kk < 16; ++kk) {
            ulonglong2 arr0 = *(const ulonglong2*)&w_rr[kk][ty4];
            ulonglong2 arr1 = *(const ulonglong2*)&w_rr[kk][ty4 + 2];
            ulonglong2 aii0 = *(const ulonglong2*)&w_ii[kk][ty4];
            ulonglong2 aii1 = *(const ulonglong2*)&w_ii[kk][ty4 + 2];
            ulonglong2 ani0 = *(const ulonglong2*)&w_ni[kk][ty4];
            ulonglong2 ani1 = *(const ulonglong2*)&w_ni[kk][ty4 + 2];
            ulonglong2 br0 = *(const ulonglong2*)&xs_r[kk][tx8];
            ulonglong2 br1 = *(const ulonglong2*)&xs_r[kk][tx8 + 4];
            ulonglong2 bi0 = *(const ulonglong2*)&xs_i[kk][tx8];
            ulonglong2 bi1 = *(const ulonglong2*)&xs_i[kk][tx8 + 4];
            ull arr[4] = {arr0.x, arr0.y, arr1.x, arr1.y};
            ull aii[4] = {aii0.x, aii0.y, aii1.x, aii1.y};
            ull ani[4] = {ani0.x, ani0.y, ani1.x, ani1.y};
            ull bre[4] = {br0.x, br0.y, br1.x, br1.y};
            ull bim[4] = {bi0.x, bi0.y, bi1.x, bi1.y};
            #pragma unroll
            for (int i = 0; i < 4; ++i)
                #pragma unroll
                for (int j = 0; j < 4; ++j) {
                    // c_re += wr*xr - wi*xi ; c_im += wr*xi + wi*xr (pairs)
                    c_re[i][j] = ffma2(arr[i], bre[j], c_re[i][j]);
                    c_re[i][j] = ffma2(ani[i], bim[j], c_re[i][j]);
                    c_im[i][j] = ffma2(arr[i], bim[j], c_im[i][j]);
                    c_im[i][j] = ffma2(aii[i], bre[j], c_im[i][j]);
                }
        }
    }

    #pragma unroll
    for (int i = 0; i < 4; ++i) {
        long row = rowBase + ty4 + i;
        #pragma unroll
        for (int j = 0; j < 4; ++j) {
            long col = colBase + tx8 + 2 * j;
            *(ull*)&g_qkv_r[row * 65536 + col] = c_re[i][j];
            *(ull*)&g_qkv_i[row * 65536 + col] = c_im[i][j];
        }
    }
}

// ---------------------------------------------------------------------------
// K2: attention per (window, head). 256 threads, dyn smem 82432 B.
// ---------------------------------------------------------------------------
__global__ __launch_bounds__(256) void attn_kernel(
    const float* __restrict__ bt, const int* __restrict__ ri,
    long btlim, long rilim)
{
    extern __shared__ __align__(16) float sm[];
    float* qr = sm;
    float* qi = qr + 2048;
    float* kr = qi + 2048;
    float* ki = kr + 2048;
    float* vr = ki + 2048;
    float* vi = vr + 2048;
    float* sr = vi + 2048;   // [64][65]
    float* si = sr + 4160;

    const int b = blockIdx.x, h = blockIdx.y;
    const int t = threadIdx.x;
    const long jb = (long)b * 64;
    const float scale = 0.17677669529663687f;   // 32^-0.5

    #pragma unroll
    for (int rep = 0; rep < 2; ++rep) {
        int slot = rep * 256 + t;
        int d = slot >> 4, n4 = (slot & 15) << 2;
        long go = (long)(h * 32 + d) * 65536 + jb + n4;
        int so = d * 64 + n4;
        *(float4*)&qr[so] = *(const float4*)&g_qkv_r[go];
        *(float4*)&qi[so] = *(const float4*)&g_qkv_i[go];
        *(float4*)&kr[so] = *(const float4*)&g_qkv_r[go + 256l * 65536];
        *(float4*)&ki[so] = *(const float4*)&g_qkv_i[go + 256l * 65536];
        *(float4*)&vr[so] = *(const float4*)&g_qkv_r[go + 512l * 65536];
        *(float4*)&vi[so] = *(const float4*)&g_qkv_i[go + 512l * 65536];
    }
    __syncthreads();

    // ---- S = scale * q conj(k)^T + bias ; micro 4n x 4m ----
    {
        const int n0 = (t >> 4) << 2, m0 = (t & 15) << 2;
        float accr[4][4] = {}, acci[4][4] = {};
        #pragma unroll 4
        for (int d = 0; d < 32; ++d) {
            float4 q4r = *(const float4*)&qr[d * 64 + n0];
            float4 q4i = *(const float4*)&qi[d * 64 + n0];
            float4 k4r = *(const float4*)&kr[d * 64 + m0];
            float4 k4i = *(const float4*)&ki[d * 64 + m0];
            float qR[4] = {q4r.x, q4r.y, q4r.z, q4r.w};
            float qI[4] = {q4i.x, q4i.y, q4i.z, q4i.w};
            float kR[4] = {k4r.x, k4r.y, k4r.z, k4r.w};
            float kI[4] = {k4i.x, k4i.y, k4i.z, k4i.w};
            #pragma unroll
            for (int i = 0; i < 4; ++i)
                #pragma unroll
                for (int j = 0; j < 4; ++j) {
                    accr[i][j] = fmaf(qR[i], kR[j], accr[i][j]);
                    accr[i][j] = fmaf(qI[i], kI[j], accr[i][j]);
                    acci[i][j] = fmaf(qI[i], kR[j], acci[i][j]);
                    acci[i][j] = fmaf(-qR[i], kI[j], acci[i][j]);
                }
        }
        #pragma unroll
        for (int i = 0; i < 4; ++i) {
            int n = n0 + i;
            #pragma unroll
            for (int j = 0; j < 4; ++j) {
                int m = m0 + j;
                int riv = gldi(ri, (long)(n << 6) + m, rilim);
                riv = riv < 0 ? 0 : (riv > 224 ? 224 : riv);
                float bv = gldf(bt, (long)riv * 8 + h, btlim);
                sr[n * 65 + m] = fmaf(accr[i][j], scale, bv);
                si[n * 65 + m] = acci[i][j] * scale;
            }
        }
    }
    __syncthreads();

    // ---- magnitude softmax + rescale (4 threads/row, 16 cols each) ----
    {
        const int row = t >> 2, c0 = (t & 3) << 4;
        float mags[16], mx = -1e30f;
        #pragma unroll
        for (int c = 0; c < 16; ++c) {
            float arr = sr[row * 65 + c0 + c], aii = si[row * 65 + c0 + c];
            float mg = sqrtf(fmaf(arr, arr, aii * aii));
            mags[c] = mg;
            mx = fmaxf(mx, mg);
        }
        mx = fmaxf(mx, __shfl_xor_sync(0xffffffffu, mx, 1));
        mx = fmaxf(mx, __shfl_xor_sync(0xffffffffu, mx, 2));
        float e[16], ssum = 0.f;
        #pragma unroll
        for (int c = 0; c < 16; ++c) { e[c] = __expf(mags[c] - mx); ssum += e[c]; }
        ssum += __shfl_xor_sync(0xffffffffu, ssum, 1);
        ssum += __shfl_xor_sync(0xffffffffu, ssum, 2);
        float inv = 1.0f / ssum;
        #pragma unroll
        for (int c = 0; c < 16; ++c) {
            float w = (e[c] * inv) / (mags[c] + 1e-8f);
            sr[row * 65 + c0 + c] *= w;
            si[row * 65 + c0 + c] *= w;
        }
    }
    __syncthreads();

    // ---- out = S @ V (64 n x 32 d); thread = (n, 8 d's) ----
    {
        const int n = t & 63, d0 = (t >> 6) << 3;
        float o_r[8] = {}, o_i[8] = {};
        #pragma unroll 4
        for (int m = 0; m < 64; ++m) {
            float srv = sr[n * 65 + m], siv = si[n * 65 + m];
            #pragma unroll
            for (int j = 0; j < 8; ++j) {
                float vrj = vr[(d0 + j) * 64 + m];
                float vij = vi[(d0 + j) * 64 + m];
                o_r[j] = fmaf(srv,  vrj, o_r[j]);
                o_r[j] = fmaf(-siv, vij, o_r[j]);
                o_i[j] = fmaf(srv,  vij, o_i[j]);
                o_i[j] = fmaf(siv,  vrj, o_i[j]);
            }
        }
        #pragma unroll
        for (int j = 0; j < 8; ++j) {
            long go = (long)(h * 32 + d0 + j) * 65536 + jb + n;
            g_att_r[go] = o_r[j];
            g_att_i[go] = o_i[j];
        }
    }
}

// ---------------------------------------------------------------------------
// K3: proj GEMM, REAL output only. Tile 64x128, K=256. Static smem 33.8 KB.
// out addr: (j>>6)*16384 + row*64 + (j&63).
// ---------------------------------------------------------------------------
__global__ __launch_bounds__(256) void proj_gemm(
    const float* __restrict__ wr, const float* __restrict__ wi,
    float* __restrict__ out, long wlim, long olim)
{
    __shared__ __align__(16) ull   w_rr[16][66], w_ni[16][66];
    __shared__ __align__(16) float xs_r[16][132], xs_i[16][132];

    const int t = threadIdx.x;
    const long colBase = (long)blockIdx.x * 128;
    const int rowBase = blockIdx.y * 64;

    const int wrow = t >> 2, wk4 = (t & 3) << 2;
    const long wbase = (long)(rowBase + wrow) * 256 + wk4;

    const int k0a = t >> 5;
    const int j0a = (t & 31) << 2;
    const long ja = colBase + j0a;

    const int tx8 = (t & 15) << 3, ty4 = (t >> 4) << 2;

    ull c_re[4][4];
    #pragma unroll
    for (int i = 0; i < 4; ++i)
        #pragma unroll
        for (int j = 0; j < 4; ++j) c_re[i][j] = 0ull;

    for (int k0 = 0; k0 < 256; k0 += 16) {
        float4 wa = guarded_ld4(wr, wbase + k0, wlim);
        float4 wb = guarded_ld4(wi, wbase + k0, wlim);
        float4 xa0 = *(const float4*)&g_att_r[(long)(k0 + k0a) * 65536 + ja];
        float4 xb0 = *(const float4*)&g_att_i[(long)(k0 + k0a) * 65536 + ja];
        float4 xa1 = *(const float4*)&g_att_r[(long)(k0 + k0a + 8) * 65536 + ja];
        float4 xb1 = *(const float4*)&g_att_i[(long)(k0 + k0a + 8) * 65536 + ja];
        __syncthreads();
        {
            float wva[4] = {wa.x, wa.y, wa.z, wa.w};
            float wvb[4] = {wb.x, wb.y, wb.z, wb.w};
            #pragma unroll
            for (int q = 0; q < 4; ++q) {
                w_rr[wk4 + q][wrow] = pk2(wva[q], wva[q]);
                w_ni[wk4 + q][wrow] = pk2(-wvb[q], -wvb[q]);
            }
            *(float4*)&xs_r[k0a][j0a] = xa0;
            *(float4*)&xs_i[k0a][j0a] = xb0;
            *(float4*)&xs_r[k0a + 8][j0a] = xa1;
            *(float4*)&xs_i[k0a + 8][j0a] = xb1;
        }
        __syncthreads();
        #pragma unroll
        for (int kk = 0; kk < 16; ++kk) {
            ulonglong2 arr0 = *(const ulonglong2*)&w_rr[kk][ty4];
            ulonglong2 arr1 = *(const ulonglong2*)&w_rr[kk][ty4 + 2];
            ulonglong2 ani0 = *(const ulonglong2*)&w_ni[kk][ty4];
            ulonglong2 ani1 = *(const ulonglong2*)&w_ni[kk][ty4 + 2];
            ulonglong2 br0 = *(const ulonglong2*)&xs_r[kk][tx8];
            ulonglong2 br1 = *(const ulonglong2*)&xs_r[kk][tx8 + 4];
            ulonglong2 bi0 = *(const ulonglong2*)&xs_i[kk][tx8];
            ulonglong2 bi1 = *(const ulonglong2*)&xs_i[kk][tx8 + 4];
            ull arr[4] = {arr0.x, arr0.y, arr1.x, arr1.y};
            ull ani[4] = {ani0.x, ani0.y, ani1.x, ani1.y};
            ull bre[4] = {br0.x, br0.y, br1.x, br1.y};
            ull bim[4] = {bi0.x, bi0.y, bi1.x, bi1.y};
            #pragma unroll
            for (int i = 0; i < 4; ++i)
                #pragma unroll
                for (int j = 0; j < 4; ++j) {
                    c_re[i][j] = ffma2(arr[i], bre[j], c_re[i][j]);
                    c_re[i][j] = ffma2(ani[i], bim[j], c_re[i][j]);
                }
        }
    }

    #pragma unroll
    for (int i = 0; i < 4; ++i) {
        long row = rowBase + ty4 + i;
        #pragma unroll
        for (int j = 0; j < 4; ++j) {
            long col = colBase + tx8 + 2 * j;
            long oaddr = (col >> 6) * 16384 + row * 64 + (col & 63);
            if (oaddr + 1 < olim) *(ull*)&out[oaddr] = c_re[i][j];
        }
    }
}

// ---------------------------------------------------------------------------
extern "C" void kernel_launch(void* const* d_in, const int* in_sizes, int n_in,
                              void* d_out, int out_size)
{
    int ord[16];
    int m = n_in < 16 ? n_in : 16;
    for (int i = 0; i < m; ++i) ord[i] = i;
    for (int i = 1; i < m; ++i) {
        int key = ord[i];
        long ks = in_sizes[key];
        int j = i - 1;
        while (j >= 0 && (long)in_sizes[ord[j]] < ks) { ord[j + 1] = ord[j]; --j; }
        ord[j + 1] = key;
    }

    const float *x_r, *x_i, *wq_r, *wq_i, *wp_r, *wp_i, *bt;
    const int* ri;
    long sx, wqlim, wplim, btlim, rilim;

    if (m >= 8) {
        int a0 = ord[0], a1 = ord[1];
        int b0 = ord[2], b1 = ord[3];
        int c0 = ord[4], c1 = ord[5];
        int r0 = ord[6], s0 = ord[7];
        if (a0 > a1) { int tt = a0; a0 = a1; a1 = tt; }
        if (b0 > b1) { int tt = b0; b0 = b1; b1 = tt; }
        if (c0 > c1) { int tt = c0; c0 = c1; c1 = tt; }
        x_r  = (const float*)d_in[a0]; x_i  = (const float*)d_in[a1];
        wq_r = (const float*)d_in[b0]; wq_i = (const float*)d_in[b1];
        wp_r = (const float*)d_in[c0]; wp_i = (const float*)d_in[c1];
        ri   = (const int*)d_in[r0];   bt   = (const float*)d_in[s0];
        sx    = in_sizes[a0];
        wqlim = in_sizes[b0] < 196608 ? in_sizes[b0] : 196608;
        wplim = in_sizes[c0] < 65536  ? in_sizes[c0] : 65536;
        rilim = in_sizes[r0] < 4096   ? in_sizes[r0] : 4096;
        btlim = in_sizes[s0] < 1800   ? in_sizes[s0] : 1800;
    } else {
        x_r  = (const float*)d_in[0]; x_i  = (const float*)d_in[1];
        wq_r = (const float*)d_in[2]; wq_i = (const float*)d_in[3];
        wp_r = (const float*)d_in[4]; wp_i = (const float*)d_in[5];
        bt   = (const float*)d_in[6]; ri   = (const int*)d_in[7];
        sx = 16777216; wqlim = 196608; wplim = 65536; rilim = 4096; btlim = 1800;
    }
    float* out = (float*)d_out;

    long B = sx / 16384;
    if (B < 1) B = 1;
    if (B > 1024) B = 1024;
    long xlim = B * 16384;
    if (xlim > sx) xlim = sx;
    long Jtot = B * 64;
    unsigned gx = (unsigned)((Jtot + 127) / 128);

    long olim = (long)out_size;
    long need = B * 16384;
    if (olim > need) olim = need;
    if (olim < 0) olim = 0;

    const int attn_smem = 82432;   // 20608 floats
    cudaFuncSetAttribute(attn_kernel,
                         cudaFuncAttributeMaxDynamicSharedMemorySize, attn_smem);

    qkv_gemm<<<dim3(gx, 12), 256>>>(wq_r, wq_i, x_r, x_i, wqlim, xlim);
    attn_kernel<<<dim3((unsigned)B, 8), 256, attn_smem>>>(bt, ri, btlim, rilim);
    proj_gemm<<<dim3(gx, 4), 256>>>(wp_r, wp_i, out, wplim, olim);
}

// round 13
// speedup vs baseline: 2.0518x; 1.0932x over previous
#include <cuda_runtime.h>

// ---------------------------------------------------------------------------
// ComplexSwinAttention — 3-kernel pipeline with packed f32x2 FMA (FFMA2).
//  K1 qkv_gemm : Wqkv(768x256 cplx) @ X(256x65536 cplx) -> g_qkv planar
//  K2 attn     : per (window, head) complex attention     -> g_att planar
//  K3 proj_gemm: Wproj(256x256 cplx) @ g_att, REAL part  -> d_out
// Round 13: __launch_bounds__(256,2) on both GEMMs -> 128 regs -> 2 CTAs/SM
// (round 12 had 140 regs -> 1 CTA/SM -> occ 12.4%, fma pipe 49.6%).
// ---------------------------------------------------------------------------

typedef unsigned long long ull;

__device__ float g_qkv_r[50331648];   // [768][65536]
__device__ float g_qkv_i[50331648];
__device__ float g_att_r[16777216];   // [256][65536]
__device__ float g_att_i[16777216];

__device__ __forceinline__ float gldf(const float* p, long off, long lim)
{
    return (off >= 0 && off < lim) ? __ldg(p + off) : 0.f;
}
__device__ __forceinline__ int gldi(const int* p, long off, long lim)
{
    return (off >= 0 && off < lim) ? __ldg(p + off) : 0;
}
__device__ __forceinline__ float4 guarded_ld4(const float* p, long off, long lim)
{
    if (off >= 0 && off + 3 < lim) return *(const float4*)(p + off);
    return make_float4(0.f, 0.f, 0.f, 0.f);
}

__device__ __forceinline__ ull pk2(float lo, float hi)
{
    ull r; asm("mov.b64 %0,{%1,%2};" : "=l"(r) : "f"(lo), "f"(hi)); return r;
}
__device__ __forceinline__ ull ffma2(ull a, ull b, ull c)
{
    ull d; asm("fma.rn.f32x2 %0,%1,%2,%3;" : "=l"(d) : "l"(a), "l"(b), "l"(c));
    return d;
}

// ---------------------------------------------------------------------------
// K1: qkv complex GEMM. Tile 64 rows x 128 cols, K=256 in 16-steps.
// 256 threads; micro = 4 rows x 4 col-pairs. Static smem 42.2 KB.
// X input layout: x[b][c][p] -> addr = (j>>6)*16384 + c*64 + (j&63).
// ---------------------------------------------------------------------------
__global__ __launch_bounds__(256, 2) void qkv_gemm(
    const float* __restrict__ wr, const float* __restrict__ wi,
    const float* __restrict__ xr, const float* __restrict__ xi,
    long wlim, long xlim)
{
    __shared__ __align__(16) ull   w_rr[16][66], w_ii[16][66], w_ni[16][66];
    __shared__ __align__(16) float xs_r[16][132], xs_i[16][132];

    const int t = threadIdx.x;
    const long colBase = (long)blockIdx.x * 128;
    const int rowBase = blockIdx.y * 64;

    const int wrow = t >> 2, wk4 = (t & 3) << 2;
    const long wbase = (long)(rowBase + wrow) * 256 + wk4;

    const int k0a = t >> 5;            // 0..7 ; second slot k0a+8
    const int j0a = (t & 31) << 2;     // 0..124
    const long ja = colBase + j0a;
    const long jblk = (ja >> 6) * 16384 + (ja & 63);

    const int tx8 = (t & 15) << 3, ty4 = (t >> 4) << 2;

    ull c_re[4][4], c_im[4][4];
    #pragma unroll
    for (int i = 0; i < 4; ++i)
        #pragma unroll
        for (int j = 0; j < 4; ++j) { c_re[i][j] = 0ull; c_im[i][j] = 0ull; }

    for (int k0 = 0; k0 < 256; k0 += 16) {
        float4 wa = guarded_ld4(wr, wbase + k0, wlim);
        float4 wb = guarded_ld4(wi, wbase + k0, wlim);
        float4 xa0 = guarded_ld4(xr, jblk + (long)(k0 + k0a) * 64, xlim);
        float4 xb0 = guarded_ld4(xi, jblk + (long)(k0 + k0a) * 64, xlim);
        float4 xa1 = guarded_ld4(xr, jblk + (long)(k0 + k0a + 8) * 64, xlim);
        float4 xb1 = guarded_ld4(xi, jblk + (long)(k0 + k0a + 8) * 64, xlim);
        __syncthreads();
        {
            float wva[4] = {wa.x, wa.y, wa.z, wa.w};
            float wvb[4] = {wb.x, wb.y, wb.z, wb.w};
            #pragma unroll
            for (int q = 0; q < 4; ++q) {
                w_rr[wk4 + q][wrow] = pk2(wva[q], wva[q]);
                w_ii[wk4 + q][wrow] = pk2(wvb[q], wvb[q]);
                w_ni[wk4 + q][wrow] = pk2(-wvb[q], -wvb[q]);
            }
            *(float4*)&xs_r[k0a][j0a] = xa0;
            *(float4*)&xs_i[k0a][j0a] = xb0;
            *(float4*)&xs_r[k0a + 8][j0a] = xa1;
            *(float4*)&xs_i[k0a + 8][j0a] = xb1;
        }
        __syncthreads();
        #pragma unroll
        for (int kk = 0; kk < 16; ++kk) {
            ulonglong2 arr0 = *(const ulonglong2*)&w_rr[kk][ty4];
            ulonglong2 arr1 = *(const ulonglong2*)&w_rr[kk][ty4 + 2];
            ulonglong2 aii0 = *(const ulonglong2*)&w_ii[kk][ty4];
            ulonglong2 aii1 = *(const ulonglong2*)&w_ii[kk][ty4 + 2];
            ulonglong2 ani0 = *(const ulonglong2*)&w_ni[kk][ty4];
            ulonglong2 ani1 = *(const ulonglong2*)&w_ni[kk][ty4 + 2];
            ulonglong2 br0 = *(const ulonglong2*)&xs_r[kk][tx8];
            ulonglong2 br1 = *(const ulonglong2*)&xs_r[kk][tx8 + 4];
            ulonglong2 bi0 = *(const ulonglong2*)&xs_i[kk][tx8];
            ulonglong2 bi1 = *(const ulonglong2*)&xs_i[kk][tx8 + 4];
            ull arr[4] = {arr0.x, arr0.y, arr1.x, arr1.y};
            ull aii[4] = {aii0.x, aii0.y, aii1.x, aii1.y};
            ull ani[4] = {ani0.x, ani0.y, ani1.x, ani1.y};
            ull bre[4] = {br0.x, br0.y, br1.x, br1.y};
            ull bim[4] = {bi0.x, bi0.y, bi1.x, bi1.y};
            #pragma unroll
            for (int i = 0; i < 4; ++i)
                #pragma unroll
                for (int j = 0; j < 4; ++j) {
                    c_re[i][j] = ffma2(arr[i], bre[j], c_re[i][j]);
                    c_re[i][j] = ffma2(ani[i], bim[j], c_re[i][j]);
                    c_im[i][j] = ffma2(arr[i], bim[j], c_im[i][j]);
                    c_im[i][j] = ffma2(aii[i], bre[j], c_im[i][j]);
                }
        }
    }

    #pragma unroll
    for (int i = 0; i < 4; ++i) {
        long row = rowBase + ty4 + i;
        #pragma unroll
        for (int j = 0; j < 4; ++j) {
            long col = colBase + tx8 + 2 * j;
            *(ull*)&g_qkv_r[row * 65536 + col] = c_re[i][j];
            *(ull*)&g_qkv_i[row * 65536 + col] = c_im[i][j];
        }
    }
}

// ---------------------------------------------------------------------------
// K2: attention per (window, head). 256 threads, dyn smem 82432 B.
// ---------------------------------------------------------------------------
__global__ __launch_bounds__(256) void attn_kernel(
    const float* __restrict__ bt, const int* __restrict__ ri,
    long btlim, long rilim)
{
    extern __shared__ __align__(16) float sm[];
    float* qr = sm;
    float* qi = qr + 2048;
    float* kr = qi + 2048;
    float* ki = kr + 2048;
    float* vr = ki + 2048;
    float* vi = vr + 2048;
    float* sr = vi + 2048;   // [64][65]
    float* si = sr + 4160;

    const int b = blockIdx.x, h = blockIdx.y;
    const int t = threadIdx.x;
    const long jb = (long)b * 64;
    const float scale = 0.17677669529663687f;   // 32^-0.5

    #pragma unroll
    for (int rep = 0; rep < 2; ++rep) {
        int slot = rep * 256 + t;
        int d = slot >> 4, n4 = (slot & 15) << 2;
        long go = (long)(h * 32 + d) * 65536 + jb + n4;
        int so = d * 64 + n4;
        *(float4*)&qr[so] = *(const float4*)&g_qkv_r[go];
        *(float4*)&qi[so] = *(const float4*)&g_qkv_i[go];
        *(float4*)&kr[so] = *(const float4*)&g_qkv_r[go + 256l * 65536];
        *(float4*)&ki[so] = *(const float4*)&g_qkv_i[go + 256l * 65536];
        *(float4*)&vr[so] = *(const float4*)&g_qkv_r[go + 512l * 65536];
        *(float4*)&vi[so] = *(const float4*)&g_qkv_i[go + 512l * 65536];
    }
    __syncthreads();

    // ---- S = scale * q conj(k)^T + bias ; micro 4n x 4m ----
    {
        const int n0 = (t >> 4) << 2, m0 = (t & 15) << 2;
        float accr[4][4] = {}, acci[4][4] = {};
        #pragma unroll 4
        for (int d = 0; d < 32; ++d) {
            float4 q4r = *(const float4*)&qr[d * 64 + n0];
            float4 q4i = *(const float4*)&qi[d * 64 + n0];
            float4 k4r = *(const float4*)&kr[d * 64 + m0];
            float4 k4i = *(const float4*)&ki[d * 64 + m0];
            float qR[4] = {q4r.x, q4r.y, q4r.z, q4r.w};
            float qI[4] = {q4i.x, q4i.y, q4i.z, q4i.w};
            float kR[4] = {k4r.x, k4r.y, k4r.z, k4r.w};
            float kI[4] = {k4i.x, k4i.y, k4i.z, k4i.w};
            #pragma unroll
            for (int i = 0; i < 4; ++i)
                #pragma unroll
                for (int j = 0; j < 4; ++j) {
                    accr[i][j] = fmaf(qR[i], kR[j], accr[i][j]);
                    accr[i][j] = fmaf(qI[i], kI[j], accr[i][j]);
                    acci[i][j] = fmaf(qI[i], kR[j], acci[i][j]);
                    acci[i][j] = fmaf(-qR[i], kI[j], acci[i][j]);
                }
        }
        #pragma unroll
        for (int i = 0; i < 4; ++i) {
            int n = n0 + i;
            #pragma unroll
            for (int j = 0; j < 4; ++j) {
                int m = m0 + j;
                int riv = gldi(ri, (long)(n << 6) + m, rilim);
                riv = riv < 0 ? 0 : (riv > 224 ? 224 : riv);
                float bv = gldf(bt, (long)riv * 8 + h, btlim);
                sr[n * 65 + m] = fmaf(accr[i][j], scale, bv);
                si[n * 65 + m] = acci[i][j] * scale;
            }
        }
    }
    __syncthreads();

    // ---- magnitude softmax + rescale (4 threads/row, 16 cols each) ----
    {
        const int row = t >> 2, c0 = (t & 3) << 4;
        float mags[16], mx = -1e30f;
        #pragma unroll
        for (int c = 0; c < 16; ++c) {
            float arr = sr[row * 65 + c0 + c], aii = si[row * 65 + c0 + c];
            float mg = sqrtf(fmaf(arr, arr, aii * aii));
            mags[c] = mg;
            mx = fmaxf(mx, mg);
        }
        mx = fmaxf(mx, __shfl_xor_sync(0xffffffffu, mx, 1));
        mx = fmaxf(mx, __shfl_xor_sync(0xffffffffu, mx, 2));
        float e[16], ssum = 0.f;
        #pragma unroll
        for (int c = 0; c < 16; ++c) { e[c] = __expf(mags[c] - mx); ssum += e[c]; }
        ssum += __shfl_xor_sync(0xffffffffu, ssum, 1);
        ssum += __shfl_xor_sync(0xffffffffu, ssum, 2);
        float inv = 1.0f / ssum;
        #pragma unroll
        for (int c = 0; c < 16; ++c) {
            float w = (e[c] * inv) / (mags[c] + 1e-8f);
            sr[row * 65 + c0 + c] *= w;
            si[row * 65 + c0 + c] *= w;
        }
    }
    __syncthreads();

    // ---- out = S @ V (64 n x 32 d); thread = (n, 8 d's) ----
    {
        const int n = t & 63, d0 = (t >> 6) << 3;
        float o_r[8] = {}, o_i[8] = {};
        #pragma unroll 4
        for (int m = 0; m < 64; ++m) {
            float srv = sr[n * 65 + m], siv = si[n * 65 + m];
            #pragma unroll
            for (int j = 0; j < 8; ++j) {
                float vrj = vr[(d0 + j) * 64 + m];
                float vij = vi[(d0 + j) * 64 + m];
                o_r[j] = fmaf(srv,  vrj, o_r[j]);
                o_r[j] = fmaf(-siv, vij, o_r[j]);
                o_i[j] = fmaf(srv,  vij, o_i[j]);
                o_i[j] = fmaf(siv,  vrj, o_i[j]);
            }
        }
        #pragma unroll
        for (int j = 0; j < 8; ++j) {
            long go = (long)(h * 32 + d0 + j) * 65536 + jb + n;
            g_att_r[go] = o_r[j];
            g_att_i[go] = o_i[j];
        }
    }
}

// ---------------------------------------------------------------------------
// K3: proj GEMM, REAL output only. Tile 64x128, K=256. Static smem 33.8 KB.
// ---------------------------------------------------------------------------
__global__ __launch_bounds__(256, 2) void proj_gemm(
    const float* __restrict__ wr, const float* __restrict__ wi,
    float* __restrict__ out, long wlim, long olim)
{
    __shared__ __align__(16) ull   w_rr[16][66], w_ni[16][66];
    __shared__ __align__(16) float xs_r[16][132], xs_i[16][132];

    const int t = threadIdx.x;
    const long colBase = (long)blockIdx.x * 128;
    const int rowBase = blockIdx.y * 64;

    const int wrow = t >> 2, wk4 = (t & 3) << 2;
    const long wbase = (long)(rowBase + wrow) * 256 + wk4;

    const int k0a = t >> 5;
    const int j0a = (t & 31) << 2;
    const long ja = colBase + j0a;

    const int tx8 = (t & 15) << 3, ty4 = (t >> 4) << 2;

    ull c_re[4][4];
    #pragma unroll
    for (int i = 0; i < 4; ++i)
        #pragma unroll
        for (int j = 0; j < 4; ++j) c_re[i][j] = 0ull;

    for (int k0 = 0; k0 < 256; k0 += 16) {
        float4 wa = guarded_ld4(wr, wbase + k0, wlim);
        float4 wb = guarded_ld4(wi, wbase + k0, wlim);
        float4 xa0 = *(const float4*)&g_att_r[(long)(k0 + k0a) * 65536 + ja];
        float4 xb0 = *(const float4*)&g_att_i[(long)(k0 + k0a) * 65536 + ja];
        float4 xa1 = *(const float4*)&g_att_r[(long)(k0 + k0a + 8) * 65536 + ja];
        float4 xb1 = *(const float4*)&g_att_i[(long)(k0 + k0a + 8) * 65536 + ja];
        __syncthreads();
        {
            float wva[4] = {wa.x, wa.y, wa.z, wa.w};
            float wvb[4] = {wb.x, wb.y, wb.z, wb.w};
            #pragma unroll
            for (int q = 0; q < 4; ++q) {
                w_rr[wk4 + q][wrow] = pk2(wva[q], wva[q]);
                w_ni[wk4 + q][wrow] = pk2(-wvb[q], -wvb[q]);
            }
            *(float4*)&xs_r[k0a][j0a] = xa0;
            *(float4*)&xs_i[k0a][j0a] = xb0;
            *(float4*)&xs_r[k0a + 8][j0a] = xa1;
            *(float4*)&xs_i[k0a + 8][j0a] = xb1;
        }
        __syncthreads();
        #pragma unroll
        for (int kk = 0; kk < 16; ++kk) {
            ulonglong2 arr0 = *(const ulonglong2*)&w_rr[kk][ty4];
            ulonglong2 arr1 = *(const ulonglong2*)&w_rr[kk][ty4 + 2];
            ulonglong2 ani0 = *(const ulonglong2*)&w_ni[kk][ty4];
            ulonglong2 ani1 = *(const ulonglong2*)&w_ni[kk][ty4 + 2];
            ulonglong2 br0 = *(const ulonglong2*)&xs_r[kk][tx8];
            ulonglong2 br1 = *(const ulonglong2*)&xs_r[kk][tx8 + 4];
            ulonglong2 bi0 = *(const ulonglong2*)&xs_i[kk][tx8];
            ulonglong2 bi1 = *(const ulonglong2*)&xs_i[kk][tx8 + 4];
            ull arr[4] = {arr0.x, arr0.y, arr1.x, arr1.y};
            ull ani[4] = {ani0.x, ani0.y, ani1.x, ani1.y};
            ull bre[4] = {br0.x, br0.y, br1.x, br1.y};
            ull bim[4] = {bi0.x, bi0.y, bi1.x, bi1.y};
            #pragma unroll
            for (int i = 0; i < 4; ++i)
                #pragma unroll
                for (int j = 0; j < 4; ++j) {
                    c_re[i][j] = ffma2(arr[i], bre[j], c_re[i][j]);
                    c_re[i][j] = ffma2(ani[i], bim[j], c_re[i][j]);
                }
        }
    }

    #pragma unroll
    for (int i = 0; i < 4; ++i) {
        long row = rowBase + ty4 + i;
        #pragma unroll
        for (int j = 0; j < 4; ++j) {
            long col = colBase + tx8 + 2 * j;
            long oaddr = (col >> 6) * 16384 + row * 64 + (col & 63);
            if (oaddr + 1 < olim) *(ull*)&out[oaddr] = c_re[i][j];
        }
    }
}

// ---------------------------------------------------------------------------
extern "C" void kernel_launch(void* const* d_in, const int* in_sizes, int n_in,
                              void* d_out, int out_size)
{
    int ord[16];
    int m = n_in < 16 ? n_in : 16;
    for (int i = 0; i < m; ++i) ord[i] = i;
    for (int i = 1; i < m; ++i) {
        int key = ord[i];
        long ks = in_sizes[key];
        int j = i - 1;
        while (j >= 0 && (long)in_sizes[ord[j]] < ks) { ord[j + 1] = ord[j]; --j; }
        ord[j + 1] = key;
    }

    const float *x_r, *x_i, *wq_r, *wq_i, *wp_r, *wp_i, *bt;
    const int* ri;
    long sx, wqlim, wplim, btlim, rilim;

    if (m >= 8) {
        int a0 = ord[0], a1 = ord[1];
        int b0 = ord[2], b1 = ord[3];
        int c0 = ord[4], c1 = ord[5];
        int r0 = ord[6], s0 = ord[7];
        if (a0 > a1) { int tt = a0; a0 = a1; a1 = tt; }
        if (b0 > b1) { int tt = b0; b0 = b1; b1 = tt; }
        if (c0 > c1) { int tt = c0; c0 = c1; c1 = tt; }
        x_r  = (const float*)d_in[a0]; x_i  = (const float*)d_in[a1];
        wq_r = (const float*)d_in[b0]; wq_i = (const float*)d_in[b1];
        wp_r = (const float*)d_in[c0]; wp_i = (const float*)d_in[c1];
        ri   = (const int*)d_in[r0];   bt   = (const float*)d_in[s0];
        sx    = in_sizes[a0];
        wqlim = in_sizes[b0] < 196608 ? in_sizes[b0] : 196608;
        wplim = in_sizes[c0] < 65536  ? in_sizes[c0] : 65536;
        rilim = in_sizes[r0] < 4096   ? in_sizes[r0] : 4096;
        btlim = in_sizes[s0] < 1800   ? in_sizes[s0] : 1800;
    } else {
        x_r  = (const float*)d_in[0]; x_i  = (const float*)d_in[1];
        wq_r = (const float*)d_in[2]; wq_i = (const float*)d_in[3];
        wp_r = (const float*)d_in[4]; wp_i = (const float*)d_in[5];
        bt   = (const float*)d_in[6]; ri   = (const int*)d_in[7];
        sx = 16777216; wqlim = 196608; wplim = 65536; rilim = 4096; btlim = 1800;
    }
    float* out = (float*)d_out;

    long B = sx / 16384;
    if (B < 1) B = 1;
    if (B > 1024) B = 1024;
    long xlim = B * 16384;
    if (xlim > sx) xlim = sx;
    long Jtot = B * 64;
    unsigned gx = (unsigned)((Jtot + 127) / 128);

    long olim = (long)out_size;
    long need = B * 16384;
    if (olim > need) olim = need;
    if (olim < 0) olim = 0;

    const int attn_smem = 82432;   // 20608 floats
    cudaFuncSetAttribute(attn_kernel,
                         cudaFuncAttributeMaxDynamicSharedMemorySize, attn_smem);

    qkv_gemm<<<dim3(gx, 12), 256>>>(wq_r, wq_i, x_r, x_i, wqlim, xlim);
    attn_kernel<<<dim3((unsigned)B, 8), 256, attn_smem>>>(bt, ri, btlim, rilim);
    proj_gemm<<<dim3(gx, 4), 256>>>(wp_r, wp_i, out, wplim, olim);
}